// round 15
// baseline (speedup 1.0000x reference)
#include <cuda_runtime.h>
#include <math.h>

#define NMAX  100000
#define NATOM 64
#define NBMAX 2048

typedef unsigned long long u64;

// Scratch (static device globals: allocation-free)
__device__ float d_lf[NMAX];
__device__ float d_red[3 * NBMAX];
__device__ float d_scal[4];

// ---------------- packed f32x2 helpers (sm_100a) ----------------
__device__ __forceinline__ u64 pk(float lo, float hi) {
    u64 r;
    asm("mov.b64 %0,{%1,%2};" : "=l"(r)
        : "r"(__float_as_uint(lo)), "r"(__float_as_uint(hi)));
    return r;
}
__device__ __forceinline__ u64 bc(float x) { return pk(x, x); }
__device__ __forceinline__ void upk(u64 p, float& lo, float& hi) {
    unsigned a, b;
    asm("mov.b64 {%0,%1},%2;" : "=r"(a), "=r"(b) : "l"(p));
    lo = __uint_as_float(a); hi = __uint_as_float(b);
}
__device__ __forceinline__ u64 ffma2(u64 a, u64 b, u64 c) {
    u64 d;
    asm("fma.rn.f32x2 %0,%1,%2,%3;" : "=l"(d) : "l"(a), "l"(b), "l"(c));
    return d;
}
__device__ __forceinline__ u64 fadd2(u64 a, u64 b) {
    u64 d;
    asm("add.rn.f32x2 %0,%1,%2;" : "=l"(d) : "l"(a), "l"(b));
    return d;
}
__device__ __forceinline__ u64 fmul2(u64 a, u64 b) {
    u64 d;
    asm("mul.rn.f32x2 %0,%1,%2;" : "=l"(d) : "l"(a), "l"(b));
    return d;
}

// ---------------- cp.async helpers ----------------
__device__ __forceinline__ void cpa16(unsigned saddr, const void* gptr) {
    asm volatile("cp.async.cg.shared.global [%0], [%1], 16;" :: "r"(saddr), "l"(gptr));
}
__device__ __forceinline__ void cp_commit() {
    asm volatile("cp.async.commit_group;");
}

// ---------------- staging buffer geometry (words), TRIPLE buffered ----------
// R: pitch 16, XOR swizzle slot = k ^ ((seg>>1)&3)  -> LDS.128 conflict-free
#define RB_PITCH 16
#define MB_PITCH 12
#define SB_PITCH 4
#define RB1 (128 * RB_PITCH)   // 2048
#define MB1 (128 * MB_PITCH)   // 1536
#define SB1 (128 * SB_PITCH)   // 512
#define R_OFF 0
#define M_OFF (3 * RB1)                 // 6144
#define S_OFF (M_OFF + 3 * MB1)         // 10752
#define DSM_WORDS (S_OFF + 3 * SB1)     // 12288 words = 49152 B dynamic
// Overlay (after staging loop): head weights in the SAME region.
#define HW1_PITCH 648   // mod 32 = 8 -> policy/value rows on disjoint banks
#define HW2_PITCH 1032  // mod 32 = 8

// ---------------------------------------------------------------------------
// One atom: e1 MLP + relu; accumulate C[l][jp] += r_l * h, rsum += r.
// R arrives packed (q01p = floats 0,1; q23p = floats 2,3): r = bc(s) * q.
// ---------------------------------------------------------------------------
__device__ __forceinline__ void proc_atom(
    float s, u64 q01p, u64 q23p,
    float m0, float m1, float m2,
    const u64 We1p[3][5], const u64 b1p[5],
    u64 C[4][5], u64 rsum[2])
{
    u64 sb_ = bc(s);
    u64 r0 = fmul2(sb_, q01p);
    u64 r1 = fmul2(sb_, q23p);
    m0 *= s; m1 *= s; m2 *= s;
    u64 mb0 = bc(m0), mb1 = bc(m1), mb2 = bc(m2);

    u64 h[5];
    #pragma unroll
    for (int p = 0; p < 5; p++) {
        u64 t = ffma2(mb0, We1p[0][p], b1p[p]);
        t = ffma2(mb1, We1p[1][p], t);
        h[p] = ffma2(mb2, We1p[2][p], t);
    }
    #pragma unroll
    for (int p = 0; p < 5; p++) {
        float lo, hi; upk(h[p], lo, hi);
        h[p] = pk(fmaxf(lo, 0.f), fmaxf(hi, 0.f));
    }

    float rs0, rs1, rs2, rs3;
    upk(r0, rs0, rs1); upk(r1, rs2, rs3);
    u64 rb;
    rb = bc(rs0);
    #pragma unroll
    for (int p = 0; p < 5; p++) C[0][p] = ffma2(rb, h[p], C[0][p]);
    rb = bc(rs1);
    #pragma unroll
    for (int p = 0; p < 5; p++) C[1][p] = ffma2(rb, h[p], C[1][p]);
    rb = bc(rs2);
    #pragma unroll
    for (int p = 0; p < 5; p++) C[2][p] = ffma2(rb, h[p], C[2][p]);
    rb = bc(rs3);
    #pragma unroll
    for (int p = 0; p < 5; p++) C[3][p] = ffma2(rb, h[p], C[3][p]);

    rsum[0] = fadd2(rsum[0], r0);
    rsum[1] = fadd2(rsum[1], r1);
}

// ---------------------------------------------------------------------------
// Main kernel: 128 threads, 64 actions/block, 2 lanes/action.
// Warp-owned staging, TRIPLE-buffered (wait depth 2 -> chunk waits hidden).
// ---------------------------------------------------------------------------
__global__ void __launch_bounds__(128, 4)
desc_main_kernel(
    const float* __restrict__ Smat, const float* __restrict__ Rraw,
    const float* __restrict__ Msk,
    const float* __restrict__ We1, const float* __restrict__ be1,
    const float* __restrict__ We2, const float* __restrict__ be2,
    const float* __restrict__ Wf1, const float* __restrict__ bf1,
    const float* __restrict__ Wf2, const float* __restrict__ bf2,
    const float* __restrict__ Wf3, const float* __restrict__ bf3,
    const float* __restrict__ Wv1, const float* __restrict__ bv1,
    const float* __restrict__ Wv2, const float* __restrict__ bv2,
    const float* __restrict__ Wv3, const float* __restrict__ bv3,
    int n_act)
{
    extern __shared__ __align__(16) float dsm[];

    __shared__ __align__(16) float sWe1[3][12];
    __shared__ __align__(16) float sWe2[10][12];
    __shared__ __align__(16) float sb1e[12], sb2e[12];
    __shared__ __align__(16) float sb1[2][32], sb2[2][32], sW3[2][32];
    __shared__ float sb3[2];
    __shared__ float s_lf[64], s_lv[64];

    const int tid = threadIdx.x;

    for (int i = tid; i < 36; i += 128)  { int r = i / 12, c = i % 12; sWe1[r][c] = (c < 10) ? We1[r * 10 + c] : 0.f; }
    for (int i = tid; i < 120; i += 128) { int r = i / 12, c = i % 12; sWe2[r][c] = (c < 10) ? We2[r * 10 + c] : 0.f; }
    for (int i = tid; i < 12; i += 128)  { sb1e[i] = (i < 10) ? be1[i] : 0.f; sb2e[i] = (i < 10) ? be2[i] : 0.f; }
    for (int i = tid; i < 32; i += 128)  { sb1[0][i] = bf1[i]; sb1[1][i] = bv1[i];
                                           sb2[0][i] = bf2[i]; sb2[1][i] = bv2[i];
                                           sW3[0][i] = Wf3[i]; sW3[1][i] = Wv3[i]; }
    if (tid == 0) { sb3[0] = bf3[0]; sb3[1] = bv3[0]; }
    __syncthreads();

    // hoist e1 weights into registers
    u64 We1p[3][5], b1p[5];
    #pragma unroll
    for (int r = 0; r < 3; r++) {
        const u64* row = reinterpret_cast<const u64*>(sWe1[r]);
        #pragma unroll
        for (int p = 0; p < 5; p++) We1p[r][p] = row[p];
    }
    {
        const u64* p1 = reinterpret_cast<const u64*>(sb1e);
        #pragma unroll
        for (int p = 0; p < 5; p++) b1p[p] = p1[p];
    }

    const int sub = tid & 1;
    const int grp = tid >> 1;
    const int act = blockIdx.x * 64 + grp;
    const bool valid = act < n_act;
    const int blk0 = blockIdx.x * 64;
    const unsigned sbase = (unsigned)__cvta_generic_to_shared(dsm);
    const int nclamp = n_act - 1;
    const int lane = tid & 31;
    const int w32  = tid & ~31;          // warp_id * 32 (segment base)

    // ---- PER-WARP copy state: warp w stages segments 32w..32w+31 ----
    // R: seg = w32 + 8r + (lane>>2); gmem float4 k = lane&3 stored at swizzled
    // slot k ^ ((seg>>1)&3). For these segs x = (lane>>3)&3 is r-invariant.
    const float* srcR[4];
    unsigned dR0;
    #pragma unroll
    for (int r = 0; r < 4; r++) {
        int sg = w32 + 8 * r + (lane >> 2);
        int a = blk0 + (sg >> 1); if (a > nclamp) a = nclamp;
        srcR[r] = Rraw + (size_t)a * 256 + (sg & 1) * 128 + (lane & 3) * 4;
    }
    {
        int sg0 = w32 + (lane >> 2);
        int slot = (lane & 3) ^ ((sg0 >> 1) & 3);
        dR0 = sbase + (unsigned)(R_OFF + sg0 * RB_PITCH + slot * 4) * 4u;
    }
    const float* srcM[3]; unsigned dM[3];
    #pragma unroll
    for (int r = 0; r < 3; r++) {
        int f = lane + 32 * r;
        int sgl = f / 3, kf = f - 3 * sgl;
        int sg = w32 + sgl;
        int a = blk0 + (sg >> 1); if (a > nclamp) a = nclamp;
        srcM[r] = Msk + (size_t)a * 192 + (sg & 1) * 96 + kf * 4;
        dM[r] = sbase + (unsigned)(M_OFF + sg * MB_PITCH + kf * 4) * 4u;
    }
    const float* srcS; unsigned dS;
    {
        int a = blk0 + (tid >> 1); if (a > nclamp) a = nclamp;
        srcS = Smat + (size_t)a * 64 + (tid & 1) * 32;
        dS = sbase + (unsigned)(S_OFF + tid * SB_PITCH) * 4u;
    }

    auto copy_chunk = [&](int buf) {
        const unsigned boR = (unsigned)(buf * RB1) * 4u;
        const unsigned boM = (unsigned)(buf * MB1) * 4u;
        const unsigned boS = (unsigned)(buf * SB1) * 4u;
        #pragma unroll
        for (int r = 0; r < 4; r++) {
            cpa16(dR0 + boR + (unsigned)r * (8u * RB_PITCH * 4u), srcR[r]);
            srcR[r] += 16;
        }
        #pragma unroll
        for (int r = 0; r < 3; r++) { cpa16(dM[r] + boM, srcM[r]); srcM[r] += 12; }
        cpa16(dS + boS, srcS); srcS += 4;
        cp_commit();
    };

    u64 C[4][5] = {};
    u64 rsum[2] = {};

    // compute-side swizzled R offsets (atom a at slot a^x)
    const int x = (tid >> 1) & 3;
    const int ro0 = (0 ^ x) << 2, ro1 = (1 ^ x) << 2;
    const int ro2 = (2 ^ x) << 2, ro3 = (3 ^ x) << 2;

    copy_chunk(0);
    copy_chunk(1);
    copy_chunk(2);

    // ---- staging loop: WARP-scoped sync only; wait depth 2 ----
    for (int c = 0; c < 8; c++) {
        if (c <= 5)      asm volatile("cp.async.wait_group 2;" ::: "memory");
        else if (c == 6) asm volatile("cp.async.wait_group 1;" ::: "memory");
        else             asm volatile("cp.async.wait_group 0;" ::: "memory");
        __syncwarp();
        const int buf = c % 3;
        const float* Rb = dsm + R_OFF + buf * RB1 + tid * RB_PITCH;
        const float* Mb = dsm + M_OFF + buf * MB1 + tid * MB_PITCH;
        const float* Sb = dsm + S_OFF + buf * SB1 + tid * SB_PITCH;
        float4 s4 = *reinterpret_cast<const float4*>(Sb);
        {
            ulonglong2 qa = *reinterpret_cast<const ulonglong2*>(Rb + ro0);
            ulonglong2 qb = *reinterpret_cast<const ulonglong2*>(Rb + ro1);
            float2 ma = *reinterpret_cast<const float2*>(Mb);
            float2 mb = *reinterpret_cast<const float2*>(Mb + 2);
            float2 mc = *reinterpret_cast<const float2*>(Mb + 4);
            proc_atom(s4.x, qa.x, qa.y, ma.x, ma.y, mb.x, We1p, b1p, C, rsum);
            proc_atom(s4.y, qb.x, qb.y, mb.y, mc.x, mc.y, We1p, b1p, C, rsum);
        }
        {
            ulonglong2 qa = *reinterpret_cast<const ulonglong2*>(Rb + ro2);
            ulonglong2 qb = *reinterpret_cast<const ulonglong2*>(Rb + ro3);
            float2 ma = *reinterpret_cast<const float2*>(Mb + 6);
            float2 mb = *reinterpret_cast<const float2*>(Mb + 8);
            float2 mc = *reinterpret_cast<const float2*>(Mb + 10);
            proc_atom(s4.z, qa.x, qa.y, ma.x, ma.y, mb.x, We1p, b1p, C, rsum);
            proc_atom(s4.w, qb.x, qb.y, mb.y, mc.x, mc.y, We1p, b1p, C, rsum);
        }
        __syncwarp();
        if (c < 5) copy_chunk((c + 3) % 3);
    }

    __syncthreads();   // all warps done with staging region

    // ---- overlay: head weights into the (now dead) staging region ----
    float* hw1 = dsm;                    // [2][HW1_PITCH]
    float* hw2 = dsm + 2 * HW1_PITCH;    // [2][HW2_PITCH]
    for (int i = tid; i < 640; i += 128)  { hw1[i] = Wf1[i]; hw1[HW1_PITCH + i] = Wv1[i]; }
    for (int i = tid; i < 1024; i += 128) { hw2[i] = Wf2[i]; hw2[HW2_PITCH + i] = Wv2[i]; }

    // ---- reduce C, rsum across the lane pair ----
    #pragma unroll
    for (int l = 0; l < 4; l++)
        #pragma unroll
        for (int p = 0; p < 5; p++)
            C[l][p] = fadd2(C[l][p], __shfl_xor_sync(0xffffffffu, C[l][p], 1));
    rsum[0] = fadd2(rsum[0], __shfl_xor_sync(0xffffffffu, rsum[0], 1));
    rsum[1] = fadd2(rsum[1], __shfl_xor_sync(0xffffffffu, rsum[1], 1));

    // ---- value lane: recompute atom 0 from gmem and exclude it ----
    if (sub == 1) {
        const int ai = valid ? act : nclamp;
        const float  s0 = Smat[(size_t)ai * 64];
        const float4 q0 = *reinterpret_cast<const float4*>(Rraw + (size_t)ai * 256);
        float m0 = Msk[(size_t)ai * 192];
        float m1 = Msk[(size_t)ai * 192 + 1];
        float m2 = Msk[(size_t)ai * 192 + 2];

        u64 r0 = pk(s0 * q0.x, s0 * q0.y);
        u64 r1 = pk(s0 * q0.z, s0 * q0.w);
        m0 *= s0; m1 *= s0; m2 *= s0;
        u64 mb0 = bc(m0), mb1 = bc(m1), mb2 = bc(m2);
        u64 h0[5];
        #pragma unroll
        for (int p = 0; p < 5; p++) {
            u64 t = ffma2(mb0, We1p[0][p], b1p[p]);
            t = ffma2(mb1, We1p[1][p], t);
            h0[p] = ffma2(mb2, We1p[2][p], t);
        }
        #pragma unroll
        for (int p = 0; p < 5; p++) {
            float lo, hi; upk(h0[p], lo, hi);
            h0[p] = pk(fmaxf(lo, 0.f), fmaxf(hi, 0.f));
        }
        float r0s[4];
        upk(r0, r0s[0], r0s[1]); upk(r1, r0s[2], r0s[3]);
        #pragma unroll
        for (int l = 0; l < 4; l++) {
            u64 rb = bc(-r0s[l]);
            #pragma unroll
            for (int p = 0; p < 5; p++)
                C[l][p] = ffma2(rb, h0[p], C[l][p]);
        }
        rsum[0] = fadd2(rsum[0], pk(-r0s[0], -r0s[1]));
        rsum[1] = fadd2(rsum[1], pk(-r0s[2], -r0s[3]));
    }

    // ---- Bm = C * We2 + rsum (x) b2 ----
    float Cs[4][10], rs[4];
    #pragma unroll
    for (int l = 0; l < 4; l++)
        #pragma unroll
        for (int p = 0; p < 5; p++)
            upk(C[l][p], Cs[l][2 * p], Cs[l][2 * p + 1]);
    upk(rsum[0], rs[0], rs[1]); upk(rsum[1], rs[2], rs[3]);

    u64 Bm[4][5];
    {
        const u64* b2pp = reinterpret_cast<const u64*>(sb2e);
        u64 b2r[5];
        #pragma unroll
        for (int p = 0; p < 5; p++) b2r[p] = b2pp[p];
        #pragma unroll
        for (int l = 0; l < 4; l++) {
            u64 rb = bc(rs[l]);
            #pragma unroll
            for (int p = 0; p < 5; p++) Bm[l][p] = fmul2(rb, b2r[p]);
        }
        #pragma unroll
        for (int j = 0; j < 10; j++) {
            const u64* row = reinterpret_cast<const u64*>(sWe2[j]);
            u64 w[5];
            #pragma unroll
            for (int p = 0; p < 5; p++) w[p] = row[p];
            #pragma unroll
            for (int l = 0; l < 4; l++) {
                u64 cb = bc(Cs[l][j]);
                #pragma unroll
                for (int p = 0; p < 5; p++) Bm[l][p] = ffma2(cb, w[p], Bm[l][p]);
            }
        }
    }

    // ---- D = A @ Bm (A[k][l] = Bm[l][k], k<2) -> x[20] ----
    float As[2][4];
    #pragma unroll
    for (int l = 0; l < 4; l++) upk(Bm[l][0], As[0][l], As[1][l]);
    u64 xp[2][5] = {};
    #pragma unroll
    for (int k = 0; k < 2; k++)
        #pragma unroll
        for (int l = 0; l < 4; l++) {
            u64 t = bc(As[k][l]);
            #pragma unroll
            for (int p = 0; p < 5; p++)
                xp[k][p] = ffma2(t, Bm[l][p], xp[k][p]);
        }
    float xs[20];
    #pragma unroll
    for (int k = 0; k < 2; k++)
        #pragma unroll
        for (int p = 0; p < 5; p++)
            upk(xp[k][p], xs[k * 10 + 2 * p], xs[k * 10 + 2 * p + 1]);

    __syncthreads();   // head weights now resident in dsm

    // ---- head MLP (sub=0 policy, sub=1 value) ----
    const float* W1 = hw1 + sub * HW1_PITCH;
    const float* W2 = hw2 + sub * HW2_PITCH;

    u64 hhp[16];
    {
        const u64* b = reinterpret_cast<const u64*>(sb1[sub]);
        #pragma unroll
        for (int q = 0; q < 16; q++) hhp[q] = b[q];
    }
    #pragma unroll 4
    for (int j = 0; j < 20; j++) {
        u64 xb = bc(xs[j]);
        const ulonglong2* wr = reinterpret_cast<const ulonglong2*>(W1 + j * 32);
        #pragma unroll
        for (int q = 0; q < 8; q++) {
            ulonglong2 w = wr[q];
            hhp[2 * q]     = ffma2(xb, w.x, hhp[2 * q]);
            hhp[2 * q + 1] = ffma2(xb, w.y, hhp[2 * q + 1]);
        }
    }
    float hs2[32];
    #pragma unroll
    for (int q = 0; q < 16; q++) {
        float lo, hi; upk(hhp[q], lo, hi);
        hs2[2 * q] = fmaxf(lo, 0.f); hs2[2 * q + 1] = fmaxf(hi, 0.f);
    }

    u64 h2p[16];
    {
        const u64* b = reinterpret_cast<const u64*>(sb2[sub]);
        #pragma unroll
        for (int q = 0; q < 16; q++) h2p[q] = b[q];
    }
    #pragma unroll 4
    for (int j = 0; j < 32; j++) {
        u64 xb = bc(hs2[j]);
        const ulonglong2* wr = reinterpret_cast<const ulonglong2*>(W2 + j * 32);
        #pragma unroll
        for (int q = 0; q < 8; q++) {
            ulonglong2 w = wr[q];
            h2p[2 * q]     = ffma2(xb, w.x, h2p[2 * q]);
            h2p[2 * q + 1] = ffma2(xb, w.y, h2p[2 * q + 1]);
        }
    }

    u64 acc = 0ull;
    {
        const u64* w3 = reinterpret_cast<const u64*>(sW3[sub]);
        #pragma unroll
        for (int q = 0; q < 16; q++) {
            float lo, hi; upk(h2p[q], lo, hi);
            acc = ffma2(pk(fmaxf(lo, 0.f), fmaxf(hi, 0.f)), w3[q], acc);
        }
    }
    float alo, ahi; upk(acc, alo, ahi);
    const float outv = sb3[sub] + alo + ahi;

    if (sub == 0) s_lf[grp] = valid ? outv : -INFINITY;
    else          s_lv[grp] = valid ? outv : 0.f;
    if (valid && sub == 0) d_lf[act] = outv;
    __syncthreads();

    // per-block online-softmax partials
    if (tid < 32) {
        float a = s_lf[tid], b = s_lf[tid + 32];
        float m = fmaxf(a, b);
        #pragma unroll
        for (int o = 16; o > 0; o >>= 1) m = fmaxf(m, __shfl_xor_sync(0xffffffffu, m, o));
        float e = __expf(a - m) + __expf(b - m);
        #pragma unroll
        for (int o = 16; o > 0; o >>= 1) e += __shfl_xor_sync(0xffffffffu, e, o);
        if (tid == 0) { d_red[blockIdx.x] = m; d_red[NBMAX + blockIdx.x] = e; }
    } else if (tid < 64) {
        int t = tid - 32;
        float v = s_lv[t] + s_lv[t + 32];
        #pragma unroll
        for (int o = 16; o > 0; o >>= 1) v += __shfl_xor_sync(0xffffffffu, v, o);
        if (t == 0) d_red[2 * NBMAX + blockIdx.x] = v;
    }
}

// ---------------------------------------------------------------------------
__global__ void k_finish(float* __restrict__ out, int n_act, int out_size, int nblk)
{
    __shared__ float sm[1024];
    const int tid = threadIdx.x;

    float m = -INFINITY;
    for (int i = tid; i < nblk; i += 1024) m = fmaxf(m, d_red[i]);
    sm[tid] = m; __syncthreads();
    for (int s = 512; s > 0; s >>= 1) { if (tid < s) sm[tid] = fmaxf(sm[tid], sm[tid + s]); __syncthreads(); }
    const float gm = sm[0];
    __syncthreads();

    float T = 0.f, V = 0.f;
    for (int i = tid; i < nblk; i += 1024) {
        T += d_red[NBMAX + i] * __expf(d_red[i] - gm);
        V += d_red[2 * NBMAX + i];
    }
    sm[tid] = T; __syncthreads();
    for (int s = 512; s > 0; s >>= 1) { if (tid < s) sm[tid] += sm[tid + s]; __syncthreads(); }
    T = sm[0];
    __syncthreads();
    sm[tid] = V; __syncthreads();
    for (int s = 512; s > 0; s >>= 1) { if (tid < s) sm[tid] += sm[tid + s]; __syncthreads(); }
    V = sm[0];

    if (tid == 0) {
        d_scal[2] = gm + logf(T);
        if (out_size > n_act) out[n_act] = V;
    }
}

__global__ void k_policy(float* __restrict__ out, int n_act)
{
    const float lse = d_scal[2];
    const int i4 = (blockIdx.x * 256 + threadIdx.x) * 4;
    if (i4 + 3 < n_act) {
        float4 v = *reinterpret_cast<const float4*>(d_lf + i4);
        v.x -= lse; v.y -= lse; v.z -= lse; v.w -= lse;
        *reinterpret_cast<float4*>(out + i4) = v;
    } else {
        for (int k = i4; k < n_act; k++) out[k] = d_lf[k] - lse;
    }
}

// ---------------------------------------------------------------------------
extern "C" void kernel_launch(void* const* d_in, const int* in_sizes, int n_in,
                              void* d_out, int out_size)
{
    const float* Smat = (const float*)d_in[0];
    const float* Rraw = (const float*)d_in[1];
    const float* Msk  = (const float*)d_in[2];
    const float* We1  = (const float*)d_in[3];
    const float* be1  = (const float*)d_in[4];
    const float* We2  = (const float*)d_in[5];
    const float* be2  = (const float*)d_in[6];
    const float* Wf1  = (const float*)d_in[7];
    const float* bf1  = (const float*)d_in[8];
    const float* Wf2  = (const float*)d_in[9];
    const float* bf2  = (const float*)d_in[10];
    const float* Wf3  = (const float*)d_in[11];
    const float* bf3  = (const float*)d_in[12];
    const float* Wv1  = (const float*)d_in[13];
    const float* bv1  = (const float*)d_in[14];
    const float* Wv2  = (const float*)d_in[15];
    const float* bv2  = (const float*)d_in[16];
    const float* Wv3  = (const float*)d_in[17];
    const float* bv3  = (const float*)d_in[18];

    int n_act = in_sizes[0] / NATOM;
    if (n_act > NMAX) n_act = NMAX;
    float* out = (float*)d_out;

    const int nblk = (n_act + 63) / 64;
    const int smem_bytes = DSM_WORDS * 4;   // 49152 B dynamic

    // Raise dynamic-smem cap (host-side attribute; not an allocation, not a
    // stream op -- safe under graph capture, idempotent across calls).
    cudaFuncSetAttribute((const void*)desc_main_kernel,
                         cudaFuncAttributeMaxDynamicSharedMemorySize, 65536);

    desc_main_kernel<<<nblk, 128, smem_bytes>>>(Smat, Rraw, Msk,
                                    We1, be1, We2, be2,
                                    Wf1, bf1, Wf2, bf2, Wf3, bf3,
                                    Wv1, bv1, Wv2, bv2, Wv3, bv3,
                                    n_act);
    k_finish<<<1, 1024>>>(out, n_act, out_size, nblk);

    const int nthr = (n_act + 3) / 4;
    k_policy<<<(nthr + 255) / 256, 256>>>(out, n_act);
}

// round 16
// speedup vs baseline: 1.0503x; 1.0503x over previous
#include <cuda_runtime.h>
#include <math.h>

#define NMAX  100000
#define NATOM 64
#define NBMAX 2048

typedef unsigned long long u64;

// Scratch (static device globals: allocation-free)
__device__ float d_lf[NMAX];
__device__ float d_red[3 * NBMAX];
__device__ float d_scal[4];

// ---------------- packed f32x2 helpers (sm_100a) ----------------
__device__ __forceinline__ u64 pk(float lo, float hi) {
    u64 r;
    asm("mov.b64 %0,{%1,%2};" : "=l"(r)
        : "r"(__float_as_uint(lo)), "r"(__float_as_uint(hi)));
    return r;
}
__device__ __forceinline__ u64 bc(float x) { return pk(x, x); }
__device__ __forceinline__ void upk(u64 p, float& lo, float& hi) {
    unsigned a, b;
    asm("mov.b64 {%0,%1},%2;" : "=r"(a), "=r"(b) : "l"(p));
    lo = __uint_as_float(a); hi = __uint_as_float(b);
}
__device__ __forceinline__ u64 ffma2(u64 a, u64 b, u64 c) {
    u64 d;
    asm("fma.rn.f32x2 %0,%1,%2,%3;" : "=l"(d) : "l"(a), "l"(b), "l"(c));
    return d;
}
__device__ __forceinline__ u64 fadd2(u64 a, u64 b) {
    u64 d;
    asm("add.rn.f32x2 %0,%1,%2;" : "=l"(d) : "l"(a), "l"(b));
    return d;
}
__device__ __forceinline__ u64 fmul2(u64 a, u64 b) {
    u64 d;
    asm("mul.rn.f32x2 %0,%1,%2;" : "=l"(d) : "l"(a), "l"(b));
    return d;
}

// ---------------- cp.async helpers ----------------
__device__ __forceinline__ void cpa16(unsigned saddr, const void* gptr) {
    asm volatile("cp.async.cg.shared.global [%0], [%1], 16;" :: "r"(saddr), "l"(gptr));
}
__device__ __forceinline__ void cp_commit() {
    asm volatile("cp.async.commit_group;");
}

// ---------------- staging buffer geometry (words) ----------------
#define RB_PITCH 20     // 16 used + 4 pad; float4 reads conflict-free
#define MB_PITCH 12     // 12 used; 16B-aligned; float2 reads conflict-free
#define SB_PITCH 4
#define RB1 (128 * RB_PITCH)   // 2560
#define MB1 (128 * MB_PITCH)   // 1536
#define SB1 (128 * SB_PITCH)   // 512
#define R_OFF 0
#define M_OFF (2 * RB1)                 // 5120
#define S_OFF (M_OFF + 2 * MB1)         // 8192
#define DSM_WORDS (S_OFF + 2 * SB1)     // 9216 words = 36864 B dynamic
// Overlay (after staging loop): head weights in the SAME region.
#define HW1_PITCH 648   // mod 32 = 8 -> policy/value rows on disjoint banks
#define HW2_PITCH 1032  // mod 32 = 8

// ---------------------------------------------------------------------------
// One atom: e1 MLP + relu; accumulate C[l][jp] += r_l * h, rsum += r.
// R comes in PACKED (q01p = floats 0,1; q23p = floats 2,3): r = bc(s) * q.
// ---------------------------------------------------------------------------
__device__ __forceinline__ void proc_atom(
    float s, u64 q01p, u64 q23p,
    float m0, float m1, float m2,
    const u64 We1p[3][5], const u64 b1p[5],
    u64 C[4][5], u64 rsum[2])
{
    u64 sb_ = bc(s);
    u64 r0 = fmul2(sb_, q01p);
    u64 r1 = fmul2(sb_, q23p);
    m0 *= s; m1 *= s; m2 *= s;
    u64 mb0 = bc(m0), mb1 = bc(m1), mb2 = bc(m2);

    u64 h[5];
    #pragma unroll
    for (int p = 0; p < 5; p++) {
        u64 t = ffma2(mb0, We1p[0][p], b1p[p]);
        t = ffma2(mb1, We1p[1][p], t);
        h[p] = ffma2(mb2, We1p[2][p], t);
    }
    #pragma unroll
    for (int p = 0; p < 5; p++) {
        float lo, hi; upk(h[p], lo, hi);
        h[p] = pk(fmaxf(lo, 0.f), fmaxf(hi, 0.f));
    }

    float rs0, rs1, rs2, rs3;
    upk(r0, rs0, rs1); upk(r1, rs2, rs3);
    u64 rb;
    rb = bc(rs0);
    #pragma unroll
    for (int p = 0; p < 5; p++) C[0][p] = ffma2(rb, h[p], C[0][p]);
    rb = bc(rs1);
    #pragma unroll
    for (int p = 0; p < 5; p++) C[1][p] = ffma2(rb, h[p], C[1][p]);
    rb = bc(rs2);
    #pragma unroll
    for (int p = 0; p < 5; p++) C[2][p] = ffma2(rb, h[p], C[2][p]);
    rb = bc(rs3);
    #pragma unroll
    for (int p = 0; p < 5; p++) C[3][p] = ffma2(rb, h[p], C[3][p]);

    rsum[0] = fadd2(rsum[0], r0);
    rsum[1] = fadd2(rsum[1], r1);
}

// ---------------------------------------------------------------------------
// Main kernel: 128 threads, 64 actions/block, 2 lanes/action.
// Warp-owned staging (warp w stages rows 32w..32w+31): staging loop uses
// __syncwarp only. 4 blocks/SM (proven best: regs ~128, no spills).
// ---------------------------------------------------------------------------
__global__ void __launch_bounds__(128, 4)
desc_main_kernel(
    const float* __restrict__ Smat, const float* __restrict__ Rraw,
    const float* __restrict__ Msk,
    const float* __restrict__ We1, const float* __restrict__ be1,
    const float* __restrict__ We2, const float* __restrict__ be2,
    const float* __restrict__ Wf1, const float* __restrict__ bf1,
    const float* __restrict__ Wf2, const float* __restrict__ bf2,
    const float* __restrict__ Wf3, const float* __restrict__ bf3,
    const float* __restrict__ Wv1, const float* __restrict__ bv1,
    const float* __restrict__ Wv2, const float* __restrict__ bv2,
    const float* __restrict__ Wv3, const float* __restrict__ bv3,
    int n_act)
{
    extern __shared__ __align__(16) float dsm[];

    __shared__ __align__(16) float sWe1[3][12];
    __shared__ __align__(16) float sWe2[10][12];
    __shared__ __align__(16) float sb1e[12], sb2e[12];
    __shared__ __align__(16) float sb1[2][32], sb2[2][32], sW3[2][32];
    __shared__ float sb3[2];
    __shared__ float s_lf[64], s_lv[64];

    const int tid = threadIdx.x;

    for (int i = tid; i < 36; i += 128)  { int r = i / 12, c = i % 12; sWe1[r][c] = (c < 10) ? We1[r * 10 + c] : 0.f; }
    for (int i = tid; i < 120; i += 128) { int r = i / 12, c = i % 12; sWe2[r][c] = (c < 10) ? We2[r * 10 + c] : 0.f; }
    for (int i = tid; i < 12; i += 128)  { sb1e[i] = (i < 10) ? be1[i] : 0.f; sb2e[i] = (i < 10) ? be2[i] : 0.f; }
    for (int i = tid; i < 32; i += 128)  { sb1[0][i] = bf1[i]; sb1[1][i] = bv1[i];
                                           sb2[0][i] = bf2[i]; sb2[1][i] = bv2[i];
                                           sW3[0][i] = Wf3[i]; sW3[1][i] = Wv3[i]; }
    if (tid == 0) { sb3[0] = bf3[0]; sb3[1] = bv3[0]; }
    __syncthreads();

    // hoist e1 weights into registers
    u64 We1p[3][5], b1p[5];
    #pragma unroll
    for (int r = 0; r < 3; r++) {
        const u64* row = reinterpret_cast<const u64*>(sWe1[r]);
        #pragma unroll
        for (int p = 0; p < 5; p++) We1p[r][p] = row[p];
    }
    {
        const u64* p1 = reinterpret_cast<const u64*>(sb1e);
        #pragma unroll
        for (int p = 0; p < 5; p++) b1p[p] = p1[p];
    }

    const int sub = tid & 1;
    const int grp = tid >> 1;
    const int act = blockIdx.x * 64 + grp;
    const bool valid = act < n_act;
    const int blk0 = blockIdx.x * 64;
    const unsigned sbase = (unsigned)__cvta_generic_to_shared(dsm);
    const int nclamp = n_act - 1;
    const int lane = tid & 31;
    const int w32  = tid & ~31;          // warp_id * 32 (segment base)

    // ---- PER-WARP copy state: warp w stages segments 32w..32w+31 ----
    const float* srcR[4];
    unsigned dR0;
    #pragma unroll
    for (int r = 0; r < 4; r++) {
        int sg = w32 + 8 * r + (lane >> 2);
        int a = blk0 + (sg >> 1); if (a > nclamp) a = nclamp;
        srcR[r] = Rraw + (size_t)a * 256 + (sg & 1) * 128 + (lane & 3) * 4;
    }
    dR0 = sbase + (unsigned)(R_OFF + (w32 + (lane >> 2)) * RB_PITCH + (lane & 3) * 4) * 4u;
    const float* srcM[3]; unsigned dM[3];
    #pragma unroll
    for (int r = 0; r < 3; r++) {
        int f = lane + 32 * r;
        int sgl = f / 3, kf = f - 3 * sgl;
        int sg = w32 + sgl;
        int a = blk0 + (sg >> 1); if (a > nclamp) a = nclamp;
        srcM[r] = Msk + (size_t)a * 192 + (sg & 1) * 96 + kf * 4;
        dM[r] = sbase + (unsigned)(M_OFF + sg * MB_PITCH + kf * 4) * 4u;
    }
    const float* srcS; unsigned dS;
    {
        int a = blk0 + (tid >> 1); if (a > nclamp) a = nclamp;
        srcS = Smat + (size_t)a * 64 + (tid & 1) * 32;
        dS = sbase + (unsigned)(S_OFF + tid * SB_PITCH) * 4u;
    }

    auto copy_chunk = [&](int buf) {
        const unsigned boR = (unsigned)(buf * RB1) * 4u;
        const unsigned boM = (unsigned)(buf * MB1) * 4u;
        const unsigned boS = (unsigned)(buf * SB1) * 4u;
        #pragma unroll
        for (int r = 0; r < 4; r++) {
            cpa16(dR0 + boR + (unsigned)r * (8u * RB_PITCH * 4u), srcR[r]);
            srcR[r] += 16;
        }
        #pragma unroll
        for (int r = 0; r < 3; r++) { cpa16(dM[r] + boM, srcM[r]); srcM[r] += 12; }
        cpa16(dS + boS, srcS); srcS += 4;
        cp_commit();
    };

    u64 C[4][5] = {};
    u64 rsum[2] = {};

    copy_chunk(0);
    copy_chunk(1);

    // ---- staging loop: WARP-scoped sync only ----
    for (int c = 0; c < 8; c++) {
        if (c < 6) asm volatile("cp.async.wait_group 1;" ::: "memory");
        else       asm volatile("cp.async.wait_group 0;" ::: "memory");
        __syncwarp();
        const int buf = c & 1;
        const float* Rb = dsm + R_OFF + buf * RB1 + tid * RB_PITCH;
        const float* Mb = dsm + M_OFF + buf * MB1 + tid * MB_PITCH;
        const float* Sb = dsm + S_OFF + buf * SB1 + tid * SB_PITCH;
        float4 s4 = *reinterpret_cast<const float4*>(Sb);
        #pragma unroll
        for (int ii = 0; ii < 2; ii++) {
            ulonglong2 qa = *reinterpret_cast<const ulonglong2*>(Rb + 8 * ii);
            ulonglong2 qb = *reinterpret_cast<const ulonglong2*>(Rb + 8 * ii + 4);
            float2 ma = *reinterpret_cast<const float2*>(Mb + 6 * ii);
            float2 mb = *reinterpret_cast<const float2*>(Mb + 6 * ii + 2);
            float2 mc = *reinterpret_cast<const float2*>(Mb + 6 * ii + 4);
            float sA = ii ? s4.z : s4.x;
            float sB = ii ? s4.w : s4.y;
            proc_atom(sA, qa.x, qa.y, ma.x, ma.y, mb.x, We1p, b1p, C, rsum);
            proc_atom(sB, qb.x, qb.y, mb.y, mc.x, mc.y, We1p, b1p, C, rsum);
        }
        __syncwarp();
        if (c < 6) copy_chunk(buf);
    }

    __syncthreads();   // all warps done with staging region

    // ---- overlay: head weights into the (now dead) staging region ----
    float* hw1 = dsm;                    // [2][HW1_PITCH]
    float* hw2 = dsm + 2 * HW1_PITCH;    // [2][HW2_PITCH]
    for (int i = tid; i < 640; i += 128)  { hw1[i] = Wf1[i]; hw1[HW1_PITCH + i] = Wv1[i]; }
    for (int i = tid; i < 1024; i += 128) { hw2[i] = Wf2[i]; hw2[HW2_PITCH + i] = Wv2[i]; }

    // ---- reduce C, rsum across the lane pair ----
    #pragma unroll
    for (int l = 0; l < 4; l++)
        #pragma unroll
        for (int p = 0; p < 5; p++)
            C[l][p] = fadd2(C[l][p], __shfl_xor_sync(0xffffffffu, C[l][p], 1));
    rsum[0] = fadd2(rsum[0], __shfl_xor_sync(0xffffffffu, rsum[0], 1));
    rsum[1] = fadd2(rsum[1], __shfl_xor_sync(0xffffffffu, rsum[1], 1));

    // ---- value lane: recompute atom 0 from gmem and exclude it ----
    if (sub == 1) {
        const int ai = valid ? act : nclamp;
        const float  s0 = Smat[(size_t)ai * 64];
        const float4 q0 = *reinterpret_cast<const float4*>(Rraw + (size_t)ai * 256);
        float m0 = Msk[(size_t)ai * 192];
        float m1 = Msk[(size_t)ai * 192 + 1];
        float m2 = Msk[(size_t)ai * 192 + 2];

        u64 r0 = pk(s0 * q0.x, s0 * q0.y);
        u64 r1 = pk(s0 * q0.z, s0 * q0.w);
        m0 *= s0; m1 *= s0; m2 *= s0;
        u64 mb0 = bc(m0), mb1 = bc(m1), mb2 = bc(m2);
        u64 h0[5];
        #pragma unroll
        for (int p = 0; p < 5; p++) {
            u64 t = ffma2(mb0, We1p[0][p], b1p[p]);
            t = ffma2(mb1, We1p[1][p], t);
            h0[p] = ffma2(mb2, We1p[2][p], t);
        }
        #pragma unroll
        for (int p = 0; p < 5; p++) {
            float lo, hi; upk(h0[p], lo, hi);
            h0[p] = pk(fmaxf(lo, 0.f), fmaxf(hi, 0.f));
        }
        float r0s[4];
        upk(r0, r0s[0], r0s[1]); upk(r1, r0s[2], r0s[3]);
        #pragma unroll
        for (int l = 0; l < 4; l++) {
            u64 rb = bc(-r0s[l]);
            #pragma unroll
            for (int p = 0; p < 5; p++)
                C[l][p] = ffma2(rb, h0[p], C[l][p]);
        }
        rsum[0] = fadd2(rsum[0], pk(-r0s[0], -r0s[1]));
        rsum[1] = fadd2(rsum[1], pk(-r0s[2], -r0s[3]));
    }

    // ---- Bm = C * We2 + rsum (x) b2 ----
    float Cs[4][10], rs[4];
    #pragma unroll
    for (int l = 0; l < 4; l++)
        #pragma unroll
        for (int p = 0; p < 5; p++)
            upk(C[l][p], Cs[l][2 * p], Cs[l][2 * p + 1]);
    upk(rsum[0], rs[0], rs[1]); upk(rsum[1], rs[2], rs[3]);

    u64 Bm[4][5];
    {
        const u64* b2pp = reinterpret_cast<const u64*>(sb2e);
        u64 b2r[5];
        #pragma unroll
        for (int p = 0; p < 5; p++) b2r[p] = b2pp[p];
        #pragma unroll
        for (int l = 0; l < 4; l++) {
            u64 rb = bc(rs[l]);
            #pragma unroll
            for (int p = 0; p < 5; p++) Bm[l][p] = fmul2(rb, b2r[p]);
        }
        #pragma unroll
        for (int j = 0; j < 10; j++) {
            const u64* row = reinterpret_cast<const u64*>(sWe2[j]);
            u64 w[5];
            #pragma unroll
            for (int p = 0; p < 5; p++) w[p] = row[p];
            #pragma unroll
            for (int l = 0; l < 4; l++) {
                u64 cb = bc(Cs[l][j]);
                #pragma unroll
                for (int p = 0; p < 5; p++) Bm[l][p] = ffma2(cb, w[p], Bm[l][p]);
            }
        }
    }

    // ---- D = A @ Bm (A[k][l] = Bm[l][k], k<2) -> x[20] ----
    float As[2][4];
    #pragma unroll
    for (int l = 0; l < 4; l++) upk(Bm[l][0], As[0][l], As[1][l]);
    u64 xp[2][5] = {};
    #pragma unroll
    for (int k = 0; k < 2; k++)
        #pragma unroll
        for (int l = 0; l < 4; l++) {
            u64 t = bc(As[k][l]);
            #pragma unroll
            for (int p = 0; p < 5; p++)
                xp[k][p] = ffma2(t, Bm[l][p], xp[k][p]);
        }
    float xs[20];
    #pragma unroll
    for (int k = 0; k < 2; k++)
        #pragma unroll
        for (int p = 0; p < 5; p++)
            upk(xp[k][p], xs[k * 10 + 2 * p], xs[k * 10 + 2 * p + 1]);

    __syncthreads();   // head weights now resident in dsm

    // ---- head MLP (sub=0 policy, sub=1 value) ----
    const float* W1 = hw1 + sub * HW1_PITCH;
    const float* W2 = hw2 + sub * HW2_PITCH;

    u64 hhp[16];
    {
        const u64* b = reinterpret_cast<const u64*>(sb1[sub]);
        #pragma unroll
        for (int q = 0; q < 16; q++) hhp[q] = b[q];
    }
    #pragma unroll 4
    for (int j = 0; j < 20; j++) {
        u64 xb = bc(xs[j]);
        const ulonglong2* wr = reinterpret_cast<const ulonglong2*>(W1 + j * 32);
        #pragma unroll
        for (int q = 0; q < 8; q++) {
            ulonglong2 w = wr[q];
            hhp[2 * q]     = ffma2(xb, w.x, hhp[2 * q]);
            hhp[2 * q + 1] = ffma2(xb, w.y, hhp[2 * q + 1]);
        }
    }
    float hs2[32];
    #pragma unroll
    for (int q = 0; q < 16; q++) {
        float lo, hi; upk(hhp[q], lo, hi);
        hs2[2 * q] = fmaxf(lo, 0.f); hs2[2 * q + 1] = fmaxf(hi, 0.f);
    }

    u64 h2p[16];
    {
        const u64* b = reinterpret_cast<const u64*>(sb2[sub]);
        #pragma unroll
        for (int q = 0; q < 16; q++) h2p[q] = b[q];
    }
    #pragma unroll 4
    for (int j = 0; j < 32; j++) {
        u64 xb = bc(hs2[j]);
        const ulonglong2* wr = reinterpret_cast<const ulonglong2*>(W2 + j * 32);
        #pragma unroll
        for (int q = 0; q < 8; q++) {
            ulonglong2 w = wr[q];
            h2p[2 * q]     = ffma2(xb, w.x, h2p[2 * q]);
            h2p[2 * q + 1] = ffma2(xb, w.y, h2p[2 * q + 1]);
        }
    }

    u64 acc = 0ull;
    {
        const u64* w3 = reinterpret_cast<const u64*>(sW3[sub]);
        #pragma unroll
        for (int q = 0; q < 16; q++) {
            float lo, hi; upk(h2p[q], lo, hi);
            acc = ffma2(pk(fmaxf(lo, 0.f), fmaxf(hi, 0.f)), w3[q], acc);
        }
    }
    float alo, ahi; upk(acc, alo, ahi);
    const float outv = sb3[sub] + alo + ahi;

    if (sub == 0) s_lf[grp] = valid ? outv : -INFINITY;
    else          s_lv[grp] = valid ? outv : 0.f;
    if (valid && sub == 0) d_lf[act] = outv;
    __syncthreads();

    // per-block online-softmax partials
    if (tid < 32) {
        float a = s_lf[tid], b = s_lf[tid + 32];
        float m = fmaxf(a, b);
        #pragma unroll
        for (int o = 16; o > 0; o >>= 1) m = fmaxf(m, __shfl_xor_sync(0xffffffffu, m, o));
        float e = __expf(a - m) + __expf(b - m);
        #pragma unroll
        for (int o = 16; o > 0; o >>= 1) e += __shfl_xor_sync(0xffffffffu, e, o);
        if (tid == 0) { d_red[blockIdx.x] = m; d_red[NBMAX + blockIdx.x] = e; }
    } else if (tid < 64) {
        int t = tid - 32;
        float v = s_lv[t] + s_lv[t + 32];
        #pragma unroll
        for (int o = 16; o > 0; o >>= 1) v += __shfl_xor_sync(0xffffffffu, v, o);
        if (t == 0) d_red[2 * NBMAX + blockIdx.x] = v;
    }
}

// ---------------------------------------------------------------------------
__global__ void k_finish(float* __restrict__ out, int n_act, int out_size, int nblk)
{
    __shared__ float sm[1024];
    const int tid = threadIdx.x;

    float m = -INFINITY;
    for (int i = tid; i < nblk; i += 1024) m = fmaxf(m, d_red[i]);
    sm[tid] = m; __syncthreads();
    for (int s = 512; s > 0; s >>= 1) { if (tid < s) sm[tid] = fmaxf(sm[tid], sm[tid + s]); __syncthreads(); }
    const float gm = sm[0];
    __syncthreads();

    float T = 0.f, V = 0.f;
    for (int i = tid; i < nblk; i += 1024) {
        T += d_red[NBMAX + i] * __expf(d_red[i] - gm);
        V += d_red[2 * NBMAX + i];
    }
    sm[tid] = T; __syncthreads();
    for (int s = 512; s > 0; s >>= 1) { if (tid < s) sm[tid] += sm[tid + s]; __syncthreads(); }
    T = sm[0];
    __syncthreads();
    sm[tid] = V; __syncthreads();
    for (int s = 512; s > 0; s >>= 1) { if (tid < s) sm[tid] += sm[tid + s]; __syncthreads(); }
    V = sm[0];

    if (tid == 0) {
        d_scal[2] = gm + logf(T);
        if (out_size > n_act) out[n_act] = V;
    }
}

__global__ void k_policy(float* __restrict__ out, int n_act)
{
    const float lse = d_scal[2];
    const int i4 = (blockIdx.x * 256 + threadIdx.x) * 4;
    if (i4 + 3 < n_act) {
        float4 v = *reinterpret_cast<const float4*>(d_lf + i4);
        v.x -= lse; v.y -= lse; v.z -= lse; v.w -= lse;
        *reinterpret_cast<float4*>(out + i4) = v;
    } else {
        for (int k = i4; k < n_act; k++) out[k] = d_lf[k] - lse;
    }
}

// ---------------------------------------------------------------------------
extern "C" void kernel_launch(void* const* d_in, const int* in_sizes, int n_in,
                              void* d_out, int out_size)
{
    const float* Smat = (const float*)d_in[0];
    const float* Rraw = (const float*)d_in[1];
    const float* Msk  = (const float*)d_in[2];
    const float* We1  = (const float*)d_in[3];
    const float* be1  = (const float*)d_in[4];
    const float* We2  = (const float*)d_in[5];
    const float* be2  = (const float*)d_in[6];
    const float* Wf1  = (const float*)d_in[7];
    const float* bf1  = (const float*)d_in[8];
    const float* Wf2  = (const float*)d_in[9];
    const float* bf2  = (const float*)d_in[10];
    const float* Wf3  = (const float*)d_in[11];
    const float* bf3  = (const float*)d_in[12];
    const float* Wv1  = (const float*)d_in[13];
    const float* bv1  = (const float*)d_in[14];
    const float* Wv2  = (const float*)d_in[15];
    const float* bv2  = (const float*)d_in[16];
    const float* Wv3  = (const float*)d_in[17];
    const float* bv3  = (const float*)d_in[18];

    int n_act = in_sizes[0] / NATOM;
    if (n_act > NMAX) n_act = NMAX;
    float* out = (float*)d_out;

    const int nblk = (n_act + 63) / 64;
    const int smem_bytes = DSM_WORDS * 4;   // 36864 B dynamic

    desc_main_kernel<<<nblk, 128, smem_bytes>>>(Smat, Rraw, Msk,
                                    We1, be1, We2, be2,
                                    Wf1, bf1, Wf2, bf2, Wf3, bf3,
                                    Wv1, bv1, Wv2, bv2, Wv3, bv3,
                                    n_act);
    k_finish<<<1, 1024>>>(out, n_act, out_size, nblk);

    const int nthr = (n_act + 3) / 4;
    k_policy<<<(nthr + 255) / 256, 256>>>(out, n_act);
}

// round 17
// speedup vs baseline: 1.0507x; 1.0004x over previous
#include <cuda_runtime.h>
#include <math.h>

#define NMAX  100000
#define NATOM 64
#define NBMAX 2048

typedef unsigned long long u64;

// Scratch (static device globals: allocation-free)
__device__ float d_lf[NMAX];
__device__ float d_red[3 * NBMAX];
__device__ float d_scal[4];

// ---------------- packed f32x2 helpers (sm_100a) ----------------
__device__ __forceinline__ u64 pk(float lo, float hi) {
    u64 r;
    asm("mov.b64 %0,{%1,%2};" : "=l"(r)
        : "r"(__float_as_uint(lo)), "r"(__float_as_uint(hi)));
    return r;
}
__device__ __forceinline__ u64 bc(float x) { return pk(x, x); }
__device__ __forceinline__ void upk(u64 p, float& lo, float& hi) {
    unsigned a, b;
    asm("mov.b64 {%0,%1},%2;" : "=r"(a), "=r"(b) : "l"(p));
    lo = __uint_as_float(a); hi = __uint_as_float(b);
}
__device__ __forceinline__ u64 ffma2(u64 a, u64 b, u64 c) {
    u64 d;
    asm("fma.rn.f32x2 %0,%1,%2,%3;" : "=l"(d) : "l"(a), "l"(b), "l"(c));
    return d;
}
__device__ __forceinline__ u64 fadd2(u64 a, u64 b) {
    u64 d;
    asm("add.rn.f32x2 %0,%1,%2;" : "=l"(d) : "l"(a), "l"(b));
    return d;
}
__device__ __forceinline__ u64 fmul2(u64 a, u64 b) {
    u64 d;
    asm("mul.rn.f32x2 %0,%1,%2;" : "=l"(d) : "l"(a), "l"(b));
    return d;
}

// ---------------- cp.async helpers ----------------
__device__ __forceinline__ void cpa16(unsigned saddr, const void* gptr) {
    asm volatile("cp.async.cg.shared.global [%0], [%1], 16;" :: "r"(saddr), "l"(gptr));
}
__device__ __forceinline__ void cp_commit() {
    asm volatile("cp.async.commit_group;");
}

// ---------------- staging buffer geometry (words) ----------------
#define RB_PITCH 20     // 16 used + 4 pad; float4 reads conflict-free
#define MB_PITCH 12     // 12 used; LDS.128 reads conflict-free (12t mod 32 distinct per phase)
#define SB_PITCH 4
#define RB1 (128 * RB_PITCH)   // 2560
#define MB1 (128 * MB_PITCH)   // 1536
#define SB1 (128 * SB_PITCH)   // 512
#define R_OFF 0
#define M_OFF (2 * RB1)                 // 5120
#define S_OFF (M_OFF + 2 * MB1)         // 8192
#define DSM_WORDS (S_OFF + 2 * SB1)     // 9216 words = 36864 B dynamic
// Overlay (after staging loop): head weights in the SAME region.
#define HW1_PITCH 648   // mod 32 = 8 -> policy/value rows on disjoint banks
#define HW2_PITCH 1032  // mod 32 = 8

// ---------------------------------------------------------------------------
// One atom: e1 MLP + relu; accumulate C[l][jp] += r_l * h, rsum += r.
// R comes in PACKED (q01p = floats 0,1; q23p = floats 2,3): r = bc(s) * q.
// ---------------------------------------------------------------------------
__device__ __forceinline__ void proc_atom(
    float s, u64 q01p, u64 q23p,
    float m0, float m1, float m2,
    const u64 We1p[3][5], const u64 b1p[5],
    u64 C[4][5], u64 rsum[2])
{
    u64 sb_ = bc(s);
    u64 r0 = fmul2(sb_, q01p);
    u64 r1 = fmul2(sb_, q23p);
    m0 *= s; m1 *= s; m2 *= s;
    u64 mb0 = bc(m0), mb1 = bc(m1), mb2 = bc(m2);

    u64 h[5];
    #pragma unroll
    for (int p = 0; p < 5; p++) {
        u64 t = ffma2(mb0, We1p[0][p], b1p[p]);
        t = ffma2(mb1, We1p[1][p], t);
        h[p] = ffma2(mb2, We1p[2][p], t);
    }
    #pragma unroll
    for (int p = 0; p < 5; p++) {
        float lo, hi; upk(h[p], lo, hi);
        h[p] = pk(fmaxf(lo, 0.f), fmaxf(hi, 0.f));
    }

    float rs0, rs1, rs2, rs3;
    upk(r0, rs0, rs1); upk(r1, rs2, rs3);
    u64 rb;
    rb = bc(rs0);
    #pragma unroll
    for (int p = 0; p < 5; p++) C[0][p] = ffma2(rb, h[p], C[0][p]);
    rb = bc(rs1);
    #pragma unroll
    for (int p = 0; p < 5; p++) C[1][p] = ffma2(rb, h[p], C[1][p]);
    rb = bc(rs2);
    #pragma unroll
    for (int p = 0; p < 5; p++) C[2][p] = ffma2(rb, h[p], C[2][p]);
    rb = bc(rs3);
    #pragma unroll
    for (int p = 0; p < 5; p++) C[3][p] = ffma2(rb, h[p], C[3][p]);

    rsum[0] = fadd2(rsum[0], r0);
    rsum[1] = fadd2(rsum[1], r1);
}

// ---------------------------------------------------------------------------
// Main kernel: 128 threads, 64 actions/block, 2 lanes/action.
// Warp-owned staging (warp w stages rows 32w..32w+31): staging loop uses
// __syncwarp only. 4 blocks/SM. M read as 3x LDS.128 (was 6x LDS.64).
// ---------------------------------------------------------------------------
__global__ void __launch_bounds__(128, 4)
desc_main_kernel(
    const float* __restrict__ Smat, const float* __restrict__ Rraw,
    const float* __restrict__ Msk,
    const float* __restrict__ We1, const float* __restrict__ be1,
    const float* __restrict__ We2, const float* __restrict__ be2,
    const float* __restrict__ Wf1, const float* __restrict__ bf1,
    const float* __restrict__ Wf2, const float* __restrict__ bf2,
    const float* __restrict__ Wf3, const float* __restrict__ bf3,
    const float* __restrict__ Wv1, const float* __restrict__ bv1,
    const float* __restrict__ Wv2, const float* __restrict__ bv2,
    const float* __restrict__ Wv3, const float* __restrict__ bv3,
    int n_act)
{
    extern __shared__ __align__(16) float dsm[];

    __shared__ __align__(16) float sWe1[3][12];
    __shared__ __align__(16) float sWe2[10][12];
    __shared__ __align__(16) float sb1e[12], sb2e[12];
    __shared__ __align__(16) float sb1[2][32], sb2[2][32], sW3[2][32];
    __shared__ float sb3[2];
    __shared__ float s_lf[64], s_lv[64];

    const int tid = threadIdx.x;

    for (int i = tid; i < 36; i += 128)  { int r = i / 12, c = i % 12; sWe1[r][c] = (c < 10) ? We1[r * 10 + c] : 0.f; }
    for (int i = tid; i < 120; i += 128) { int r = i / 12, c = i % 12; sWe2[r][c] = (c < 10) ? We2[r * 10 + c] : 0.f; }
    for (int i = tid; i < 12; i += 128)  { sb1e[i] = (i < 10) ? be1[i] : 0.f; sb2e[i] = (i < 10) ? be2[i] : 0.f; }
    for (int i = tid; i < 32; i += 128)  { sb1[0][i] = bf1[i]; sb1[1][i] = bv1[i];
                                           sb2[0][i] = bf2[i]; sb2[1][i] = bv2[i];
                                           sW3[0][i] = Wf3[i]; sW3[1][i] = Wv3[i]; }
    if (tid == 0) { sb3[0] = bf3[0]; sb3[1] = bv3[0]; }
    __syncthreads();

    // hoist e1 weights into registers
    u64 We1p[3][5], b1p[5];
    #pragma unroll
    for (int r = 0; r < 3; r++) {
        const u64* row = reinterpret_cast<const u64*>(sWe1[r]);
        #pragma unroll
        for (int p = 0; p < 5; p++) We1p[r][p] = row[p];
    }
    {
        const u64* p1 = reinterpret_cast<const u64*>(sb1e);
        #pragma unroll
        for (int p = 0; p < 5; p++) b1p[p] = p1[p];
    }

    const int sub = tid & 1;
    const int grp = tid >> 1;
    const int act = blockIdx.x * 64 + grp;
    const bool valid = act < n_act;
    const int blk0 = blockIdx.x * 64;
    const unsigned sbase = (unsigned)__cvta_generic_to_shared(dsm);
    const int nclamp = n_act - 1;
    const int lane = tid & 31;
    const int w32  = tid & ~31;          // warp_id * 32 (segment base)

    // ---- PER-WARP copy state: warp w stages segments 32w..32w+31 ----
    const float* srcR[4];
    unsigned dR0;
    #pragma unroll
    for (int r = 0; r < 4; r++) {
        int sg = w32 + 8 * r + (lane >> 2);
        int a = blk0 + (sg >> 1); if (a > nclamp) a = nclamp;
        srcR[r] = Rraw + (size_t)a * 256 + (sg & 1) * 128 + (lane & 3) * 4;
    }
    dR0 = sbase + (unsigned)(R_OFF + (w32 + (lane >> 2)) * RB_PITCH + (lane & 3) * 4) * 4u;
    const float* srcM[3]; unsigned dM[3];
    #pragma unroll
    for (int r = 0; r < 3; r++) {
        int f = lane + 32 * r;
        int sgl = f / 3, kf = f - 3 * sgl;
        int sg = w32 + sgl;
        int a = blk0 + (sg >> 1); if (a > nclamp) a = nclamp;
        srcM[r] = Msk + (size_t)a * 192 + (sg & 1) * 96 + kf * 4;
        dM[r] = sbase + (unsigned)(M_OFF + sg * MB_PITCH + kf * 4) * 4u;
    }
    const float* srcS; unsigned dS;
    {
        int a = blk0 + (tid >> 1); if (a > nclamp) a = nclamp;
        srcS = Smat + (size_t)a * 64 + (tid & 1) * 32;
        dS = sbase + (unsigned)(S_OFF + tid * SB_PITCH) * 4u;
    }

    auto copy_chunk = [&](int buf) {
        const unsigned boR = (unsigned)(buf * RB1) * 4u;
        const unsigned boM = (unsigned)(buf * MB1) * 4u;
        const unsigned boS = (unsigned)(buf * SB1) * 4u;
        #pragma unroll
        for (int r = 0; r < 4; r++) {
            cpa16(dR0 + boR + (unsigned)r * (8u * RB_PITCH * 4u), srcR[r]);
            srcR[r] += 16;
        }
        #pragma unroll
        for (int r = 0; r < 3; r++) { cpa16(dM[r] + boM, srcM[r]); srcM[r] += 12; }
        cpa16(dS + boS, srcS); srcS += 4;
        cp_commit();
    };

    u64 C[4][5] = {};
    u64 rsum[2] = {};

    copy_chunk(0);
    copy_chunk(1);

    // ---- staging loop: WARP-scoped sync only ----
    for (int c = 0; c < 8; c++) {
        if (c < 6) asm volatile("cp.async.wait_group 1;" ::: "memory");
        else       asm volatile("cp.async.wait_group 0;" ::: "memory");
        __syncwarp();
        const int buf = c & 1;
        const float* Rb = dsm + R_OFF + buf * RB1 + tid * RB_PITCH;
        const float* Mb = dsm + M_OFF + buf * MB1 + tid * MB_PITCH;
        const float* Sb = dsm + S_OFF + buf * SB1 + tid * SB_PITCH;
        float4 s4 = *reinterpret_cast<const float4*>(Sb);
        // M: 12 words via 3 LDS.128 (conflict-free; scalars fall out in order)
        float4 v0 = *reinterpret_cast<const float4*>(Mb);
        float4 v1 = *reinterpret_cast<const float4*>(Mb + 4);
        float4 v2 = *reinterpret_cast<const float4*>(Mb + 8);
        {
            ulonglong2 qa = *reinterpret_cast<const ulonglong2*>(Rb);
            ulonglong2 qb = *reinterpret_cast<const ulonglong2*>(Rb + 4);
            proc_atom(s4.x, qa.x, qa.y, v0.x, v0.y, v0.z, We1p, b1p, C, rsum);
            proc_atom(s4.y, qb.x, qb.y, v0.w, v1.x, v1.y, We1p, b1p, C, rsum);
        }
        {
            ulonglong2 qa = *reinterpret_cast<const ulonglong2*>(Rb + 8);
            ulonglong2 qb = *reinterpret_cast<const ulonglong2*>(Rb + 12);
            proc_atom(s4.z, qa.x, qa.y, v1.z, v1.w, v2.x, We1p, b1p, C, rsum);
            proc_atom(s4.w, qb.x, qb.y, v2.y, v2.z, v2.w, We1p, b1p, C, rsum);
        }
        __syncwarp();
        if (c < 6) copy_chunk(buf);
    }

    __syncthreads();   // all warps done with staging region

    // ---- overlay: head weights into the (now dead) staging region ----
    float* hw1 = dsm;                    // [2][HW1_PITCH]
    float* hw2 = dsm + 2 * HW1_PITCH;    // [2][HW2_PITCH]
    for (int i = tid; i < 640; i += 128)  { hw1[i] = Wf1[i]; hw1[HW1_PITCH + i] = Wv1[i]; }
    for (int i = tid; i < 1024; i += 128) { hw2[i] = Wf2[i]; hw2[HW2_PITCH + i] = Wv2[i]; }

    // ---- reduce C, rsum across the lane pair ----
    #pragma unroll
    for (int l = 0; l < 4; l++)
        #pragma unroll
        for (int p = 0; p < 5; p++)
            C[l][p] = fadd2(C[l][p], __shfl_xor_sync(0xffffffffu, C[l][p], 1));
    rsum[0] = fadd2(rsum[0], __shfl_xor_sync(0xffffffffu, rsum[0], 1));
    rsum[1] = fadd2(rsum[1], __shfl_xor_sync(0xffffffffu, rsum[1], 1));

    // ---- value lane: recompute atom 0 from gmem and exclude it ----
    if (sub == 1) {
        const int ai = valid ? act : nclamp;
        const float  s0 = Smat[(size_t)ai * 64];
        const float4 q0 = *reinterpret_cast<const float4*>(Rraw + (size_t)ai * 256);
        float m0 = Msk[(size_t)ai * 192];
        float m1 = Msk[(size_t)ai * 192 + 1];
        float m2 = Msk[(size_t)ai * 192 + 2];

        u64 r0 = pk(s0 * q0.x, s0 * q0.y);
        u64 r1 = pk(s0 * q0.z, s0 * q0.w);
        m0 *= s0; m1 *= s0; m2 *= s0;
        u64 mb0 = bc(m0), mb1 = bc(m1), mb2 = bc(m2);
        u64 h0[5];
        #pragma unroll
        for (int p = 0; p < 5; p++) {
            u64 t = ffma2(mb0, We1p[0][p], b1p[p]);
            t = ffma2(mb1, We1p[1][p], t);
            h0[p] = ffma2(mb2, We1p[2][p], t);
        }
        #pragma unroll
        for (int p = 0; p < 5; p++) {
            float lo, hi; upk(h0[p], lo, hi);
            h0[p] = pk(fmaxf(lo, 0.f), fmaxf(hi, 0.f));
        }
        float r0s[4];
        upk(r0, r0s[0], r0s[1]); upk(r1, r0s[2], r0s[3]);
        #pragma unroll
        for (int l = 0; l < 4; l++) {
            u64 rb = bc(-r0s[l]);
            #pragma unroll
            for (int p = 0; p < 5; p++)
                C[l][p] = ffma2(rb, h0[p], C[l][p]);
        }
        rsum[0] = fadd2(rsum[0], pk(-r0s[0], -r0s[1]));
        rsum[1] = fadd2(rsum[1], pk(-r0s[2], -r0s[3]));
    }

    // ---- Bm = C * We2 + rsum (x) b2 ----
    float Cs[4][10], rs[4];
    #pragma unroll
    for (int l = 0; l < 4; l++)
        #pragma unroll
        for (int p = 0; p < 5; p++)
            upk(C[l][p], Cs[l][2 * p], Cs[l][2 * p + 1]);
    upk(rsum[0], rs[0], rs[1]); upk(rsum[1], rs[2], rs[3]);

    u64 Bm[4][5];
    {
        const u64* b2pp = reinterpret_cast<const u64*>(sb2e);
        u64 b2r[5];
        #pragma unroll
        for (int p = 0; p < 5; p++) b2r[p] = b2pp[p];
        #pragma unroll
        for (int l = 0; l < 4; l++) {
            u64 rb = bc(rs[l]);
            #pragma unroll
            for (int p = 0; p < 5; p++) Bm[l][p] = fmul2(rb, b2r[p]);
        }
        #pragma unroll
        for (int j = 0; j < 10; j++) {
            const u64* row = reinterpret_cast<const u64*>(sWe2[j]);
            u64 w[5];
            #pragma unroll
            for (int p = 0; p < 5; p++) w[p] = row[p];
            #pragma unroll
            for (int l = 0; l < 4; l++) {
                u64 cb = bc(Cs[l][j]);
                #pragma unroll
                for (int p = 0; p < 5; p++) Bm[l][p] = ffma2(cb, w[p], Bm[l][p]);
            }
        }
    }

    // ---- D = A @ Bm (A[k][l] = Bm[l][k], k<2) -> x[20] ----
    float As[2][4];
    #pragma unroll
    for (int l = 0; l < 4; l++) upk(Bm[l][0], As[0][l], As[1][l]);
    u64 xp[2][5] = {};
    #pragma unroll
    for (int k = 0; k < 2; k++)
        #pragma unroll
        for (int l = 0; l < 4; l++) {
            u64 t = bc(As[k][l]);
            #pragma unroll
            for (int p = 0; p < 5; p++)
                xp[k][p] = ffma2(t, Bm[l][p], xp[k][p]);
        }
    float xs[20];
    #pragma unroll
    for (int k = 0; k < 2; k++)
        #pragma unroll
        for (int p = 0; p < 5; p++)
            upk(xp[k][p], xs[k * 10 + 2 * p], xs[k * 10 + 2 * p + 1]);

    __syncthreads();   // head weights now resident in dsm

    // ---- head MLP (sub=0 policy, sub=1 value) ----
    const float* W1 = hw1 + sub * HW1_PITCH;
    const float* W2 = hw2 + sub * HW2_PITCH;

    u64 hhp[16];
    {
        const u64* b = reinterpret_cast<const u64*>(sb1[sub]);
        #pragma unroll
        for (int q = 0; q < 16; q++) hhp[q] = b[q];
    }
    #pragma unroll 4
    for (int j = 0; j < 20; j++) {
        u64 xb = bc(xs[j]);
        const ulonglong2* wr = reinterpret_cast<const ulonglong2*>(W1 + j * 32);
        #pragma unroll
        for (int q = 0; q < 8; q++) {
            ulonglong2 w = wr[q];
            hhp[2 * q]     = ffma2(xb, w.x, hhp[2 * q]);
            hhp[2 * q + 1] = ffma2(xb, w.y, hhp[2 * q + 1]);
        }
    }
    float hs2[32];
    #pragma unroll
    for (int q = 0; q < 16; q++) {
        float lo, hi; upk(hhp[q], lo, hi);
        hs2[2 * q] = fmaxf(lo, 0.f); hs2[2 * q + 1] = fmaxf(hi, 0.f);
    }

    u64 h2p[16];
    {
        const u64* b = reinterpret_cast<const u64*>(sb2[sub]);
        #pragma unroll
        for (int q = 0; q < 16; q++) h2p[q] = b[q];
    }
    #pragma unroll 4
    for (int j = 0; j < 32; j++) {
        u64 xb = bc(hs2[j]);
        const ulonglong2* wr = reinterpret_cast<const ulonglong2*>(W2 + j * 32);
        #pragma unroll
        for (int q = 0; q < 8; q++) {
            ulonglong2 w = wr[q];
            h2p[2 * q]     = ffma2(xb, w.x, h2p[2 * q]);
            h2p[2 * q + 1] = ffma2(xb, w.y, h2p[2 * q + 1]);
        }
    }

    u64 acc = 0ull;
    {
        const u64* w3 = reinterpret_cast<const u64*>(sW3[sub]);
        #pragma unroll
        for (int q = 0; q < 16; q++) {
            float lo, hi; upk(h2p[q], lo, hi);
            acc = ffma2(pk(fmaxf(lo, 0.f), fmaxf(hi, 0.f)), w3[q], acc);
        }
    }
    float alo, ahi; upk(acc, alo, ahi);
    const float outv = sb3[sub] + alo + ahi;

    if (sub == 0) s_lf[grp] = valid ? outv : -INFINITY;
    else          s_lv[grp] = valid ? outv : 0.f;
    if (valid && sub == 0) d_lf[act] = outv;
    __syncthreads();

    // per-block online-softmax partials
    if (tid < 32) {
        float a = s_lf[tid], b = s_lf[tid + 32];
        float m = fmaxf(a, b);
        #pragma unroll
        for (int o = 16; o > 0; o >>= 1) m = fmaxf(m, __shfl_xor_sync(0xffffffffu, m, o));
        float e = __expf(a - m) + __expf(b - m);
        #pragma unroll
        for (int o = 16; o > 0; o >>= 1) e += __shfl_xor_sync(0xffffffffu, e, o);
        if (tid == 0) { d_red[blockIdx.x] = m; d_red[NBMAX + blockIdx.x] = e; }
    } else if (tid < 64) {
        int t = tid - 32;
        float v = s_lv[t] + s_lv[t + 32];
        #pragma unroll
        for (int o = 16; o > 0; o >>= 1) v += __shfl_xor_sync(0xffffffffu, v, o);
        if (t == 0) d_red[2 * NBMAX + blockIdx.x] = v;
    }
}

// ---------------------------------------------------------------------------
__global__ void k_finish(float* __restrict__ out, int n_act, int out_size, int nblk)
{
    __shared__ float sm[1024];
    const int tid = threadIdx.x;

    float m = -INFINITY;
    for (int i = tid; i < nblk; i += 1024) m = fmaxf(m, d_red[i]);
    sm[tid] = m; __syncthreads();
    for (int s = 512; s > 0; s >>= 1) { if (tid < s) sm[tid] = fmaxf(sm[tid], sm[tid + s]); __syncthreads(); }
    const float gm = sm[0];
    __syncthreads();

    float T = 0.f, V = 0.f;
    for (int i = tid; i < nblk; i += 1024) {
        T += d_red[NBMAX + i] * __expf(d_red[i] - gm);
        V += d_red[2 * NBMAX + i];
    }
    sm[tid] = T; __syncthreads();
    for (int s = 512; s > 0; s >>= 1) { if (tid < s) sm[tid] += sm[tid + s]; __syncthreads(); }
    T = sm[0];
    __syncthreads();
    sm[tid] = V; __syncthreads();
    for (int s = 512; s > 0; s >>= 1) { if (tid < s) sm[tid] += sm[tid + s]; __syncthreads(); }
    V = sm[0];

    if (tid == 0) {
        d_scal[2] = gm + logf(T);
        if (out_size > n_act) out[n_act] = V;
    }
}

__global__ void k_policy(float* __restrict__ out, int n_act)
{
    const float lse = d_scal[2];
    const int i4 = (blockIdx.x * 256 + threadIdx.x) * 4;
    if (i4 + 3 < n_act) {
        float4 v = *reinterpret_cast<const float4*>(d_lf + i4);
        v.x -= lse; v.y -= lse; v.z -= lse; v.w -= lse;
        *reinterpret_cast<float4*>(out + i4) = v;
    } else {
        for (int k = i4; k < n_act; k++) out[k] = d_lf[k] - lse;
    }
}

// ---------------------------------------------------------------------------
extern "C" void kernel_launch(void* const* d_in, const int* in_sizes, int n_in,
                              void* d_out, int out_size)
{
    const float* Smat = (const float*)d_in[0];
    const float* Rraw = (const float*)d_in[1];
    const float* Msk  = (const float*)d_in[2];
    const float* We1  = (const float*)d_in[3];
    const float* be1  = (const float*)d_in[4];
    const float* We2  = (const float*)d_in[5];
    const float* be2  = (const float*)d_in[6];
    const float* Wf1  = (const float*)d_in[7];
    const float* bf1  = (const float*)d_in[8];
    const float* Wf2  = (const float*)d_in[9];
    const float* bf2  = (const float*)d_in[10];
    const float* Wf3  = (const float*)d_in[11];
    const float* bf3  = (const float*)d_in[12];
    const float* Wv1  = (const float*)d_in[13];
    const float* bv1  = (const float*)d_in[14];
    const float* Wv2  = (const float*)d_in[15];
    const float* bv2  = (const float*)d_in[16];
    const float* Wv3  = (const float*)d_in[17];
    const float* bv3  = (const float*)d_in[18];

    int n_act = in_sizes[0] / NATOM;
    if (n_act > NMAX) n_act = NMAX;
    float* out = (float*)d_out;

    const int nblk = (n_act + 63) / 64;
    const int smem_bytes = DSM_WORDS * 4;   // 36864 B dynamic

    desc_main_kernel<<<nblk, 128, smem_bytes>>>(Smat, Rraw, Msk,
                                    We1, be1, We2, be2,
                                    Wf1, bf1, Wf2, bf2, Wf3, bf3,
                                    Wv1, bv1, Wv2, bv2, Wv3, bv3,
                                    n_act);
    k_finish<<<1, 1024>>>(out, n_act, out_size, nblk);

    const int nthr = (n_act + 3) / 4;
    k_policy<<<(nthr + 255) / 256, 256>>>(out, n_act);
}